// round 5
// baseline (speedup 1.0000x reference)
#include <cuda_runtime.h>
#include <math.h>

#define NB   8
#define CC   256
#define HH   192
#define WW   320
#define FHH  768
#define FWW  1280
#define HWc  (HH*WW)          // 61440 coarse pixels
#define NHW  (NB*HWc)         // 491520
#define FHW  (FHH*FWW)        // 983040 fine pixels
#define FUSED_ELEMS ((size_t)NB*CC*HWc)   // 125,829,120
#define CH   16               // channels per block in fuse
#define CHUNKS (CC/CH)        // 16
#define HALF (HWc/2)          // 30720

// Precomputed per-(n,h,w):
//   g_w: (b*w00, b*w01, b*w10, b*w11) — bilinear weights * rm1n/s, invalid taps zeroed
//   g_o: (off00, dx, dyW, float_as_int(a)) — clamped tap base + steps + rm1/s
__device__ float4 g_w[NHW];
__device__ int4   g_o[NHW];

// -------------------------------------------------------------------------
// Kernel 1: per coarse pixel param computation.
// Bilinear resize 768x1280 -> 192x320 is exactly the mean of the 2x2 block
// at (4h+1, 4w+1) (fractional weights are exactly 0.5).
// -------------------------------------------------------------------------
__global__ void params_kernel(const float* __restrict__ flow,
                              const float* __restrict__ mask1,
                              const float* __restrict__ mask1n)
{
    int idx = blockIdx.x * blockDim.x + threadIdx.x;
    if (idx >= NHW) return;
    int w = idx % WW;
    int h = (idx / WW) % HH;
    int n = idx / HWc;

    size_t o00 = (size_t)(4*h + 1) * FWW + (4*w + 1);

    // resized flow (mean of 4) * component scale (0.25) => 0.0625 * sum4
    const float* flx = flow + (size_t)n * 2 * FHW;
    const float* fly = flx + (size_t)FHW;
    float rfx = 0.0625f * (flx[o00] + flx[o00+1] + flx[o00+FWW] + flx[o00+FWW+1]);
    float rfy = 0.0625f * (fly[o00] + fly[o00+1] + fly[o00+FWW] + fly[o00+FWW+1]);

    // grid_sample pixel coords
    float px = ((float)w + rfx) * ((float)WW / (float)(WW-1)) - 0.5f;
    float py = ((float)h + rfy) * ((float)HH / (float)(HH-1)) - 0.5f;

    // rm1: resized mask1 at this pixel
    const float* m1 = mask1 + (size_t)n * FHW;
    float rm1 = 0.25f * (m1[o00] + m1[o00+1] + m1[o00+FWW] + m1[o00+FWW+1]);

    int   x0 = (int)floorf(px);
    int   y0 = (int)floorf(py);
    float wx = px - (float)x0;
    float wy = py - (float)y0;

    // rm1n: grid_sample (zeros padding) of resized mask1_next at (px,py)
    const float* mn = mask1n + (size_t)n * FHW;
    float v00 = 0.f, v01 = 0.f, v10 = 0.f, v11 = 0.f;
    bool yv0 = (y0 >= 0)   & (y0 < HH);
    bool yv1 = (y0+1 >= 0) & (y0+1 < HH);
    bool xv0 = (x0 >= 0)   & (x0 < WW);
    bool xv1 = (x0+1 >= 0) & (x0+1 < WW);
    if (yv0 & xv0) { size_t o = (size_t)(4*y0+1)*FWW + (4*x0+1);
        v00 = 0.25f*(mn[o]+mn[o+1]+mn[o+FWW]+mn[o+FWW+1]); }
    if (yv0 & xv1) { size_t o = (size_t)(4*y0+1)*FWW + (4*(x0+1)+1);
        v01 = 0.25f*(mn[o]+mn[o+1]+mn[o+FWW]+mn[o+FWW+1]); }
    if (yv1 & xv0) { size_t o = (size_t)(4*(y0+1)+1)*FWW + (4*x0+1);
        v10 = 0.25f*(mn[o]+mn[o+1]+mn[o+FWW]+mn[o+FWW+1]); }
    if (yv1 & xv1) { size_t o = (size_t)(4*(y0+1)+1)*FWW + (4*(x0+1)+1);
        v11 = 0.25f*(mn[o]+mn[o+1]+mn[o+FWW]+mn[o+FWW+1]); }

    float rm1n = v00*(1.f-wx)*(1.f-wy) + v01*wx*(1.f-wy)
               + v10*(1.f-wx)*wy       + v11*wx*wy;

    float s = rm1 + rm1n;
    if (s == 0.0f) s = 1e-6f;
    float a = rm1 / s;
    float b = rm1n / s;

    // Fold validity into weights; fold b in too. Clamp offsets so loads stay
    // in-plane (value irrelevant when weight==0).
    int x0c = min(max(x0, 0), WW-1);
    int x1c = min(max(x0+1, 0), WW-1);
    int y0c = min(max(y0, 0), HH-1);
    int y1c = min(max(y0+1, 0), HH-1);

    float w00 = (yv0 & xv0) ? b*(1.f-wx)*(1.f-wy) : 0.f;
    float w01 = (yv0 & xv1) ? b*wx*(1.f-wy)       : 0.f;
    float w10 = (yv1 & xv0) ? b*(1.f-wx)*wy       : 0.f;
    float w11 = (yv1 & xv1) ? b*wx*wy             : 0.f;

    g_w[idx] = make_float4(w00, w01, w10, w11);
    g_o[idx] = make_int4(y0c*WW + x0c, x1c - x0c, (y1c - y0c)*WW,
                         __float_as_int(a));
}

// -------------------------------------------------------------------------
// Kernel 2: fused = a*fmap1 + sum(w_i * fmap1n taps). Each thread owns TWO
// spatial pixels half a plane apart (both warp-coalesced: consecutive lanes
// -> consecutive pixels), looping CH channels via pointer increments.
// Doubles per-thread MLP to cover L2 gather latency.
// -------------------------------------------------------------------------
__global__ void __launch_bounds__(256) fuse_kernel(
        const float* __restrict__ fmap1,
        const float* __restrict__ fmap1n,
        float* __restrict__ out)
{
    int sp    = blockIdx.x * 256 + threadIdx.x;   // spatial pixel, < HWc/2
    int n     = blockIdx.y / CHUNKS;
    int cbase = (blockIdx.y % CHUNKS) * CH;

    float4 wv0 = g_w[n * HWc + sp];
    int4   ov0 = g_o[n * HWc + sp];
    float4 wv1 = g_w[n * HWc + sp + HALF];
    int4   ov1 = g_o[n * HWc + sp + HALF];
    float  a0  = __int_as_float(ov0.w);
    float  a1  = __int_as_float(ov1.w);

    size_t plane = ((size_t)(n * CC + cbase)) * HWc;
    const float* f1 = fmap1  + plane + sp;
    const float* fn = fmap1n + plane;
    float*       o  = out    + plane + sp;

    #pragma unroll 4
    for (int c = 0; c < CH; c++) {
        // pixel 0
        float t00 = __ldg(fn + ov0.x);
        float t01 = __ldg(fn + ov0.x + ov0.y);
        float t10 = __ldg(fn + ov0.x + ov0.z);
        float t11 = __ldg(fn + ov0.x + ov0.z + ov0.y);
        // pixel 1 (independent chain)
        float u00 = __ldg(fn + ov1.x);
        float u01 = __ldg(fn + ov1.x + ov1.y);
        float u10 = __ldg(fn + ov1.x + ov1.z);
        float u11 = __ldg(fn + ov1.x + ov1.z + ov1.y);
        float f0  = f1[0];
        float fh  = f1[HALF];

        float r0 = a0 * f0
                 + wv0.x * t00 + wv0.y * t01 + wv0.z * t10 + wv0.w * t11;
        float r1 = a1 * fh
                 + wv1.x * u00 + wv1.y * u01 + wv1.z * u10 + wv1.w * u11;
        o[0]    = r0;
        o[HALF] = r1;
        f1 += HWc; fn += HWc; o += HWc;
    }
}

// -------------------------------------------------------------------------
// Kernel 3: convex upsample of coarse flow channel 0, factor 4.
// One thread per (n, yf, w): produces the 4 fx outputs (contiguous float4).
// mask layout: [N, 9*4*4, H, W], channel = k*16 + fy*4 + fx.
// -------------------------------------------------------------------------
__global__ void upsample_kernel(const float* __restrict__ cflow,
                                const float* __restrict__ umask,
                                float* __restrict__ out)
{
    int idx = blockIdx.x * blockDim.x + threadIdx.x;
    int total = NB * FHH * WW;
    if (idx >= total) return;
    int w  = idx % WW;
    int yf = (idx / WW) % FHH;
    int n  = idx / (WW * FHH);
    int h = yf >> 2, fy = yf & 3;

    // shared 3x3 flow neighborhood (channel 0), zero-padded
    const float* fb = cflow + (size_t)n * 2 * HWc;
    float fv[9];
    #pragma unroll
    for (int k = 0; k < 9; k++) {
        int dy = k / 3 - 1, dxk = k % 3 - 1;
        int hh = h + dy, ww = w + dxk;
        fv[k] = ((hh >= 0) & (hh < HH) & (ww >= 0) & (ww < WW))
                  ? fb[hh * WW + ww] : 0.f;
    }

    const float* mb = umask + (size_t)n * 144 * HWc
                            + (size_t)(fy * 4) * HWc
                            + (size_t)h * WW + w;
    float4 res;
    float* resp = (float*)&res;
    #pragma unroll
    for (int fx = 0; fx < 4; fx++) {
        float m[9];
        float mx = -1e30f;
        #pragma unroll
        for (int k = 0; k < 9; k++) {
            m[k] = mb[(size_t)(k * 16 + fx) * HWc];
            mx = fmaxf(mx, m[k]);
        }
        float num = 0.f, den = 0.f;
        #pragma unroll
        for (int k = 0; k < 9; k++) {
            float e = __expf(m[k] - mx);
            den += e;
            num += e * fv[k];
        }
        resp[fx] = 4.0f * num / den;
    }

    float4* op = (float4*)(out + (size_t)n * FHW + (size_t)yf * FWW + 4 * w);
    *op = res;
}

// -------------------------------------------------------------------------
extern "C" void kernel_launch(void* const* d_in, const int* in_sizes, int n_in,
                              void* d_out, int out_size)
{
    const float* fmap1   = (const float*)d_in[0];
    const float* fmap1n  = (const float*)d_in[1];
    const float* flow    = (const float*)d_in[2];
    const float* mask1   = (const float*)d_in[3];
    const float* mask1n  = (const float*)d_in[4];
    const float* cflow   = (const float*)d_in[5];
    const float* umask   = (const float*)d_in[6];

    float* out_fused = (float*)d_out;
    float* out_flow  = out_fused + FUSED_ELEMS;

    const int T = 256;
    params_kernel<<<(NHW + T - 1) / T, T>>>(flow, mask1, mask1n);

    dim3 fg(HALF / 256, NB * CHUNKS);   // (120, 128)
    fuse_kernel<<<fg, 256>>>(fmap1, fmap1n, out_fused);

    int utotal = NB * FHH * WW;
    upsample_kernel<<<(utotal + T - 1) / T, T>>>(cflow, umask, out_flow);
}

// round 6
// speedup vs baseline: 1.0999x; 1.0999x over previous
#include <cuda_runtime.h>
#include <math.h>

#define NB   8
#define CC   256
#define HH   192
#define WW   320
#define FHH  768
#define FWW  1280
#define HWc  (HH*WW)          // 61440 coarse pixels
#define NHW  (NB*HWc)         // 491520
#define FHW  (FHH*FWW)        // 983040 fine pixels
#define FUSED_ELEMS ((size_t)NB*CC*HWc)   // 125,829,120
#define CH   16               // channels per block in fuse
#define CHUNKS (CC/CH)        // 16

// Precomputed per-(n,h,w):
//   g_w: (b*w00, b*w01, b*w10, b*w11) — bilinear weights * rm1n/s, invalid taps zeroed
//   g_o: (off00, dx, dyW, float_as_int(a)) — clamped tap base + steps + rm1/s
__device__ float4 g_w[NHW];
__device__ int4   g_o[NHW];

// -------------------------------------------------------------------------
// Kernel 1: per coarse pixel param computation.
// Bilinear resize 768x1280 -> 192x320 is exactly the mean of the 2x2 block
// at (4h+1, 4w+1) (fractional weights are exactly 0.5).
// -------------------------------------------------------------------------
__global__ void params_kernel(const float* __restrict__ flow,
                              const float* __restrict__ mask1,
                              const float* __restrict__ mask1n)
{
    int idx = blockIdx.x * blockDim.x + threadIdx.x;
    if (idx >= NHW) return;
    int w = idx % WW;
    int h = (idx / WW) % HH;
    int n = idx / HWc;

    size_t o00 = (size_t)(4*h + 1) * FWW + (4*w + 1);

    // resized flow (mean of 4) * component scale (0.25) => 0.0625 * sum4
    const float* flx = flow + (size_t)n * 2 * FHW;
    const float* fly = flx + (size_t)FHW;
    float rfx = 0.0625f * (flx[o00] + flx[o00+1] + flx[o00+FWW] + flx[o00+FWW+1]);
    float rfy = 0.0625f * (fly[o00] + fly[o00+1] + fly[o00+FWW] + fly[o00+FWW+1]);

    // grid_sample pixel coords
    float px = ((float)w + rfx) * ((float)WW / (float)(WW-1)) - 0.5f;
    float py = ((float)h + rfy) * ((float)HH / (float)(HH-1)) - 0.5f;

    // rm1: resized mask1 at this pixel
    const float* m1 = mask1 + (size_t)n * FHW;
    float rm1 = 0.25f * (m1[o00] + m1[o00+1] + m1[o00+FWW] + m1[o00+FWW+1]);

    int   x0 = (int)floorf(px);
    int   y0 = (int)floorf(py);
    float wx = px - (float)x0;
    float wy = py - (float)y0;

    // rm1n: grid_sample (zeros padding) of resized mask1_next at (px,py)
    const float* mn = mask1n + (size_t)n * FHW;
    float v00 = 0.f, v01 = 0.f, v10 = 0.f, v11 = 0.f;
    bool yv0 = (y0 >= 0)   & (y0 < HH);
    bool yv1 = (y0+1 >= 0) & (y0+1 < HH);
    bool xv0 = (x0 >= 0)   & (x0 < WW);
    bool xv1 = (x0+1 >= 0) & (x0+1 < WW);
    if (yv0 & xv0) { size_t o = (size_t)(4*y0+1)*FWW + (4*x0+1);
        v00 = 0.25f*(mn[o]+mn[o+1]+mn[o+FWW]+mn[o+FWW+1]); }
    if (yv0 & xv1) { size_t o = (size_t)(4*y0+1)*FWW + (4*(x0+1)+1);
        v01 = 0.25f*(mn[o]+mn[o+1]+mn[o+FWW]+mn[o+FWW+1]); }
    if (yv1 & xv0) { size_t o = (size_t)(4*(y0+1)+1)*FWW + (4*x0+1);
        v10 = 0.25f*(mn[o]+mn[o+1]+mn[o+FWW]+mn[o+FWW+1]); }
    if (yv1 & xv1) { size_t o = (size_t)(4*(y0+1)+1)*FWW + (4*(x0+1)+1);
        v11 = 0.25f*(mn[o]+mn[o+1]+mn[o+FWW]+mn[o+FWW+1]); }

    float rm1n = v00*(1.f-wx)*(1.f-wy) + v01*wx*(1.f-wy)
               + v10*(1.f-wx)*wy       + v11*wx*wy;

    float s = rm1 + rm1n;
    if (s == 0.0f) s = 1e-6f;
    float a = rm1 / s;
    float b = rm1n / s;

    // Fold validity into weights; fold b in too. Clamp offsets so loads stay
    // in-plane (value irrelevant when weight==0).
    int x0c = min(max(x0, 0), WW-1);
    int x1c = min(max(x0+1, 0), WW-1);
    int y0c = min(max(y0, 0), HH-1);
    int y1c = min(max(y0+1, 0), HH-1);

    float w00 = (yv0 & xv0) ? b*(1.f-wx)*(1.f-wy) : 0.f;
    float w01 = (yv0 & xv1) ? b*wx*(1.f-wy)       : 0.f;
    float w10 = (yv1 & xv0) ? b*(1.f-wx)*wy       : 0.f;
    float w11 = (yv1 & xv1) ? b*wx*wy             : 0.f;

    g_w[idx] = make_float4(w00, w01, w10, w11);
    g_o[idx] = make_int4(y0c*WW + x0c, x1c - x0c, (y1c - y0c)*WW,
                         __float_as_int(a));
}

// -------------------------------------------------------------------------
// Kernel 2: fused = a*fmap1 + sum(w_i * fmap1n taps). One thread per spatial
// pixel (consecutive lanes -> consecutive pixels: gather stays coalesced),
// looping CH channels via pointer increments. Forced to 32 regs so 8 blocks
// (2048 threads) fit per SM — more warps to cover the L2 gather latency.
// -------------------------------------------------------------------------
__global__ void __launch_bounds__(256, 8) fuse_kernel(
        const float* __restrict__ fmap1,
        const float* __restrict__ fmap1n,
        float* __restrict__ out)
{
    int sp    = blockIdx.x * 256 + threadIdx.x;   // spatial pixel, < HWc
    int n     = blockIdx.y / CHUNKS;
    int cbase = (blockIdx.y % CHUNKS) * CH;

    float4 wv = g_w[n * HWc + sp];
    int4   ov = g_o[n * HWc + sp];
    float  a  = __int_as_float(ov.w);
    int o00 = ov.x, dx = ov.y, dyw = ov.z;

    size_t plane = ((size_t)(n * CC + cbase)) * HWc;
    const float* f1 = fmap1  + plane + sp;
    const float* fn = fmap1n + plane;
    float*       o  = out    + plane + sp;

    #pragma unroll 4
    for (int c = 0; c < CH; c++) {
        float t00 = fn[o00];
        float t01 = fn[o00 + dx];
        float t10 = fn[o00 + dyw];
        float t11 = fn[o00 + dyw + dx];
        float r = a * f1[0]
                + wv.x * t00 + wv.y * t01 + wv.z * t10 + wv.w * t11;
        o[0] = r;
        f1 += HWc; fn += HWc; o += HWc;
    }
}

// -------------------------------------------------------------------------
// Kernel 3: convex upsample of coarse flow channel 0, factor 4.
// One thread per (n, yf, w): produces the 4 fx outputs (contiguous float4).
// mask layout: [N, 9*4*4, H, W], channel = k*16 + fy*4 + fx.
// -------------------------------------------------------------------------
__global__ void upsample_kernel(const float* __restrict__ cflow,
                                const float* __restrict__ umask,
                                float* __restrict__ out)
{
    int idx = blockIdx.x * blockDim.x + threadIdx.x;
    int total = NB * FHH * WW;
    if (idx >= total) return;
    int w  = idx % WW;
    int yf = (idx / WW) % FHH;
    int n  = idx / (WW * FHH);
    int h = yf >> 2, fy = yf & 3;

    // shared 3x3 flow neighborhood (channel 0), zero-padded
    const float* fb = cflow + (size_t)n * 2 * HWc;
    float fv[9];
    #pragma unroll
    for (int k = 0; k < 9; k++) {
        int dy = k / 3 - 1, dxk = k % 3 - 1;
        int hh = h + dy, ww = w + dxk;
        fv[k] = ((hh >= 0) & (hh < HH) & (ww >= 0) & (ww < WW))
                  ? fb[hh * WW + ww] : 0.f;
    }

    const float* mb = umask + (size_t)n * 144 * HWc
                            + (size_t)(fy * 4) * HWc
                            + (size_t)h * WW + w;
    float4 res;
    float* resp = (float*)&res;
    #pragma unroll
    for (int fx = 0; fx < 4; fx++) {
        float m[9];
        float mx = -1e30f;
        #pragma unroll
        for (int k = 0; k < 9; k++) {
            m[k] = mb[(size_t)(k * 16 + fx) * HWc];
            mx = fmaxf(mx, m[k]);
        }
        float num = 0.f, den = 0.f;
        #pragma unroll
        for (int k = 0; k < 9; k++) {
            float e = __expf(m[k] - mx);
            den += e;
            num += e * fv[k];
        }
        resp[fx] = 4.0f * num / den;
    }

    float4* op = (float4*)(out + (size_t)n * FHW + (size_t)yf * FWW + 4 * w);
    *op = res;
}

// -------------------------------------------------------------------------
extern "C" void kernel_launch(void* const* d_in, const int* in_sizes, int n_in,
                              void* d_out, int out_size)
{
    const float* fmap1   = (const float*)d_in[0];
    const float* fmap1n  = (const float*)d_in[1];
    const float* flow    = (const float*)d_in[2];
    const float* mask1   = (const float*)d_in[3];
    const float* mask1n  = (const float*)d_in[4];
    const float* cflow   = (const float*)d_in[5];
    const float* umask   = (const float*)d_in[6];

    float* out_fused = (float*)d_out;
    float* out_flow  = out_fused + FUSED_ELEMS;

    const int T = 256;
    params_kernel<<<(NHW + T - 1) / T, T>>>(flow, mask1, mask1n);

    dim3 fg(HWc / 256, NB * CHUNKS);   // (240, 128)
    fuse_kernel<<<fg, 256>>>(fmap1, fmap1n, out_fused);

    int utotal = NB * FHH * WW;
    upsample_kernel<<<(utotal + T - 1) / T, T>>>(cflow, umask, out_flow);
}